// round 15
// baseline (speedup 1.0000x reference)
#include <cuda_runtime.h>
#include <cuda_fp16.h>
#include <stdint.h>
#include <math.h>

#define SEQ    2048
#define DH     64
#define NBH    32
#define DM     1024
#define NROWS  4096
#define STRB   144          // smem row stride in bytes (72 halves)
#define TILEB  (128 * STRB) // one 128x64 fp16 tile (padded)
#define HTILEB (64 * STRB)  // one 64x64 fp16 tile

// ---------------- global scratch (fp16) + dataflow flags ----------------
__device__ __half g_Kf[NBH * SEQ * DH];
__device__ __half g_Vf[NBH * SEQ * DH];
__device__ __half g_Wf[DM * DM];
__device__ __half g_xf[NROWS * DM];
__device__ int g_headcnt[NBH];   // # attn blocks done for head h
__device__ int g_masknz;         // 1 if any mask element nonzero (0-init; OR-only)

// ---------------- helpers ----------------
__device__ __forceinline__ uint32_t smem_u32(const void* p) {
    uint32_t a;
    asm("{ .reg .u64 t; cvta.to.shared.u64 t, %1; cvt.u32.u64 %0, t; }" : "=r"(a) : "l"(p));
    return a;
}
__device__ __forceinline__ uint32_t lds_addr(uint32_t base, int r0, int c0, int lane) {
    return base + (uint32_t)(r0 + (lane & 15)) * STRB + (uint32_t)(c0 + ((lane >> 4) << 3)) * 2u;
}
__device__ __forceinline__ void ldsm4(uint32_t* r, uint32_t addr) {
    asm volatile("ldmatrix.sync.aligned.m8n8.x4.shared.b16 {%0,%1,%2,%3}, [%4];"
                 : "=r"(r[0]), "=r"(r[1]), "=r"(r[2]), "=r"(r[3]) : "r"(addr));
}
__device__ __forceinline__ void ldsm4t(uint32_t* r, uint32_t addr) {
    asm volatile("ldmatrix.sync.aligned.m8n8.x4.trans.shared.b16 {%0,%1,%2,%3}, [%4];"
                 : "=r"(r[0]), "=r"(r[1]), "=r"(r[2]), "=r"(r[3]) : "r"(addr));
}
__device__ __forceinline__ void mma16816(float* c, const uint32_t* a, uint32_t b0, uint32_t b1) {
    asm volatile("mma.sync.aligned.m16n8k16.row.col.f32.f16.f16.f32 "
                 "{%0,%1,%2,%3}, {%4,%5,%6,%7}, {%8,%9}, {%0,%1,%2,%3};"
                 : "+f"(c[0]), "+f"(c[1]), "+f"(c[2]), "+f"(c[3])
                 : "r"(a[0]), "r"(a[1]), "r"(a[2]), "r"(a[3]), "r"(b0), "r"(b1));
}
__device__ __forceinline__ uint32_t pack2(float f0, float f1) {
    __half2 h = __floats2half2_rn(f0, f1);
    return *(uint32_t*)&h;
}
__device__ __forceinline__ void cp16(uint32_t dst, const void* src) {
    asm volatile("cp.async.ca.shared.global [%0], [%1], 16;" :: "r"(dst), "l"(src));
}
#define CP_COMMIT() asm volatile("cp.async.commit_group;" ::: "memory")
#define CP_WAIT0()  asm volatile("cp.async.wait_group 0;" ::: "memory")

// stage a [128 x 64 fp32] tile into padded fp16 smem, converting on the fly
__device__ __forceinline__ void stage_tile_f32(char* dst, const float* __restrict__ src) {
    for (int i = threadIdx.x; i < 128 * 8; i += 256) {
        const int r = i >> 3, s = i & 7;
        const float4 a = *(const float4*)(src + (size_t)r * 64 + s * 8);
        const float4 b = *(const float4*)(src + (size_t)r * 64 + s * 8 + 4);
        uint4 o;
        o.x = pack2(a.x, a.y); o.y = pack2(a.z, a.w);
        o.z = pack2(b.x, b.y); o.w = pack2(b.z, b.w);
        *(uint4*)(dst + r * STRB + s * 16) = o;
    }
}
__device__ __forceinline__ void stage_async(uint32_t dst, const __half* __restrict__ src,
                                            int gstride, int rows) {
    for (int i = threadIdx.x; i < rows * 8; i += 256) {
        const int r = i >> 3, s = i & 7;
        cp16(dst + (uint32_t)(r * STRB + s * 16), src + (size_t)r * gstride + s * 8);
    }
}

// ---------------- preprocessing: K/V/W convert + mask scan + flag reset ----------------
#define NQ (NBH * SEQ * DH)
__global__ void conv_all(const float* __restrict__ K, const float* __restrict__ V,
                         const float* __restrict__ W, const float* __restrict__ mask) {
    if (blockIdx.x == 0 && threadIdx.x < NBH) g_headcnt[threadIdx.x] = 0;
    const int total8 = (2 * NQ + DM * DM) / 8;
    for (int i = blockIdx.x * blockDim.x + threadIdx.x; i < total8; i += gridDim.x * blockDim.x) {
        const int base = i * 8;
        const float* src; __half* dst; int idx;
        if (base < NQ)            { src = K; dst = g_Kf; idx = base; }
        else if (base < 2 * NQ)   { src = V; dst = g_Vf; idx = base - NQ; }
        else                      { src = W; dst = g_Wf; idx = base - 2 * NQ; }
        const float4 a = *(const float4*)(src + idx);
        const float4 b = *(const float4*)(src + idx + 4);
        uint4 o;
        o.x = pack2(a.x, a.y); o.y = pack2(a.z, a.w);
        o.z = pack2(b.x, b.y); o.w = pack2(b.z, b.w);
        *(uint4*)(dst + idx) = o;
    }
    // scan mask (S*S floats) for any nonzero
    int nz = 0;
    const int m4 = (SEQ * SEQ) / 4;
    for (int i = blockIdx.x * blockDim.x + threadIdx.x; i < m4; i += gridDim.x * blockDim.x) {
        const float4 m = ((const float4*)mask)[i];
        nz |= (m.x != 0.0f) | (m.y != 0.0f) | (m.z != 0.0f) | (m.w != 0.0f);
    }
    if (__syncthreads_or(nz)) {
        if (threadIdx.x == 0) atomicOr(&g_masknz, 1);
    }
}

// ---------------- fused: attn blocks [0,512) | gemm blocks [512,1024) ----------------
__global__ void __launch_bounds__(256, 2) attn_gemm(const float* __restrict__ Q,
                                                    const float* __restrict__ mask,
                                                    const float* __restrict__ bias,
                                                    float* __restrict__ out) {
    extern __shared__ char smem[];
    const uint32_t sb = smem_u32(smem);
    const int blk = blockIdx.x;
    const int tid = threadIdx.x;
    const int wid = tid >> 5, lane = tid & 31;
    const int grp = lane >> 2, qd = (lane & 3) * 2;

    if (blk < 512) {
        // ================= attention =================
        const int bh = blk >> 4;          // head-major: head 0 completes first
        const int q0 = (blk & 15) * 128;
        const size_t hbase = (size_t)bh * (SEQ * DH);
        const __half* Kh = g_Kf + hbase;
        const __half* Vh = g_Vf + hbase;
        const int masknz = g_masknz;

        const uint32_t bK[2] = { sb,         sb + 2 * TILEB };
        const uint32_t bV[2] = { sb + TILEB, sb + 3 * TILEB };

        // stage Q directly from fp32 (converted in place; used once, no scratch trip)
        uint32_t qa[4][4];
        stage_tile_f32(smem, Q + hbase + (size_t)q0 * DH);
        __syncthreads();
#pragma unroll
        for (int dc = 0; dc < 4; ++dc) ldsm4(qa[dc], lds_addr(bK[0], wid * 16, dc * 16, lane));
        __syncthreads();

        stage_async(bK[0], Kh, 64, 128);
        stage_async(bV[0], Vh, 64, 128);
        CP_COMMIT();

        float o[8][4];
#pragma unroll
        for (int n = 0; n < 8; ++n)
#pragma unroll
            for (int j = 0; j < 4; ++j) o[n][j] = 0.0f;
        float sum0 = 0.0f, sum1 = 0.0f;

        const float* mbase = mask + (size_t)(q0 + wid * 16 + grp) * SEQ + qd;

        for (int t = 0; t < SEQ / 128; ++t) {
            CP_WAIT0();
            __syncthreads();
            if (t + 1 < SEQ / 128) {
                const size_t nkoff = (size_t)(t + 1) * 128 * DH;
                stage_async(bK[(t + 1) & 1], Kh + nkoff, 64, 128);
                stage_async(bV[(t + 1) & 1], Vh + nkoff, 64, 128);
            }
            CP_COMMIT();

            const uint32_t cK = bK[t & 1], cV = bV[t & 1];

#pragma unroll
            for (int kc = 0; kc < 8; ++kc) {
                float c0[4] = {0, 0, 0, 0}, c1[4] = {0, 0, 0, 0};
                uint32_t kb[4][4];
#pragma unroll
                for (int dc = 0; dc < 4; ++dc) ldsm4(kb[dc], lds_addr(cK, kc * 16, dc * 16, lane));
#pragma unroll
                for (int dc = 0; dc < 4; ++dc) {
                    mma16816(c0, qa[dc], kb[dc][0], kb[dc][2]);
                    mma16816(c1, qa[dc], kb[dc][1], kb[dc][3]);
                }

                // ---- scale (+ mask only if any nonzero) + exp ----
                float l00 = c0[0] * 0.125f, l01 = c0[1] * 0.125f;
                float l02 = c0[2] * 0.125f, l03 = c0[3] * 0.125f;
                float l10 = c1[0] * 0.125f, l11 = c1[1] * 0.125f;
                float l12 = c1[2] * 0.125f, l13 = c1[3] * 0.125f;
                if (masknz) {
                    const float* mrow = mbase + t * 128 + kc * 16;
                    const float2 m0 = __ldg((const float2*)(mrow));
                    const float2 m1 = __ldg((const float2*)(mrow + 8));
                    const float2 m2 = __ldg((const float2*)(mrow + 8 * SEQ));
                    const float2 m3 = __ldg((const float2*)(mrow + 8 * SEQ + 8));
                    l00 += m0.x; l01 += m0.y; l02 += m2.x; l03 += m2.y;
                    l10 += m1.x; l11 += m1.y; l12 += m3.x; l13 += m3.y;
                }
                const float p00 = __expf(l00);
                const float p01 = __expf(l01);
                const float p02 = __expf(l02);
                const float p03 = __expf(l03);
                const float p10 = __expf(l10);
                const float p11 = __expf(l11);
                const float p12 = __expf(l12);
                const float p13 = __expf(l13);
                sum0 += p00 + p01 + p10 + p11;
                sum1 += p02 + p03 + p12 + p13;

                uint32_t pa[4];
                pa[0] = pack2(p00, p01); pa[1] = pack2(p02, p03);
                pa[2] = pack2(p10, p11); pa[3] = pack2(p12, p13);

                uint32_t vb[4][4];
#pragma unroll
                for (int g = 0; g < 4; ++g) ldsm4t(vb[g], lds_addr(cV, kc * 16, g * 16, lane));
#pragma unroll
                for (int g = 0; g < 4; ++g) {
                    mma16816(o[2 * g],     pa, vb[g][0], vb[g][1]);
                    mma16816(o[2 * g + 1], pa, vb[g][2], vb[g][3]);
                }
            }
            __syncthreads();
        }

        sum0 += __shfl_xor_sync(0xffffffffu, sum0, 1);
        sum0 += __shfl_xor_sync(0xffffffffu, sum0, 2);
        sum1 += __shfl_xor_sync(0xffffffffu, sum1, 1);
        sum1 += __shfl_xor_sync(0xffffffffu, sum1, 2);
        const float inv0 = 1.0f / sum0, inv1 = 1.0f / sum1;

        const size_t r0o = hbase + (size_t)(q0 + wid * 16 + grp) * DH + qd;
        const size_t r1o = r0o + 8 * DH;
#pragma unroll
        for (int n = 0; n < 8; ++n) {
            *(uint32_t*)(g_xf + r0o + n * 8) = pack2(o[n][0] * inv0, o[n][1] * inv0);
            *(uint32_t*)(g_xf + r1o + n * 8) = pack2(o[n][2] * inv1, o[n][3] * inv1);
        }
        // release: make x visible, then count this block for its head
        __threadfence();
        __syncthreads();
        if (tid == 0) atomicAdd(&g_headcnt[bh], 1);
        return;
    }

    // ================= output projection =================
    {
        const int u  = blk - 512;
        const int g  = u >> 4;            // head-major: matches attn completion order
        const int j0 = (u & 15) * 64;
        const int i0 = g * 128;

        // acquire: head g's 16 attn blocks done
        if (tid == 0) {
            while (atomicAdd(&g_headcnt[g], 0) < 16) __nanosleep(200);
            __threadfence();
        }
        __syncthreads();

        const uint32_t bA[2] = { sb,         sb + TILEB + HTILEB };
        const uint32_t bB[2] = { sb + TILEB, sb + 2 * TILEB + HTILEB };

        float o[8][4];
#pragma unroll
        for (int n = 0; n < 8; ++n)
#pragma unroll
            for (int j = 0; j < 4; ++j) o[n][j] = 0.0f;

        stage_async(bA[0], g_xf + (size_t)i0 * DM, DM, 128);
        stage_async(bB[0], g_Wf + (size_t)j0 * DM, DM, 64);
        CP_COMMIT();

        for (int ks = 0; ks < DM / 64; ++ks) {
            CP_WAIT0();
            __syncthreads();
            if (ks + 1 < DM / 64) {
                stage_async(bA[(ks + 1) & 1], g_xf + (size_t)i0 * DM + (ks + 1) * 64, DM, 128);
                stage_async(bB[(ks + 1) & 1], g_Wf + (size_t)j0 * DM + (ks + 1) * 64, DM, 64);
            }
            CP_COMMIT();

            const uint32_t cA = bA[ks & 1], cB = bB[ks & 1];
            uint32_t aa[4][4];
#pragma unroll
            for (int dc = 0; dc < 4; ++dc) ldsm4(aa[dc], lds_addr(cA, wid * 16, dc * 16, lane));
#pragma unroll
            for (int dc = 0; dc < 4; ++dc) {
#pragma unroll
                for (int nb = 0; nb < 4; ++nb) {
                    uint32_t bb[4];
                    ldsm4(bb, lds_addr(cB, nb * 16, dc * 16, lane));
                    mma16816(o[2 * nb],     aa[dc], bb[0], bb[2]);
                    mma16816(o[2 * nb + 1], aa[dc], bb[1], bb[3]);
                }
            }
            __syncthreads();
        }

        const int r0 = i0 + wid * 16 + grp;
#pragma unroll
        for (int n = 0; n < 8; ++n) {
            const int col = j0 + n * 8 + qd;
            const float2 bb = __ldg((const float2*)&bias[col]);
            float2 v0 = make_float2(o[n][0] + bb.x, o[n][1] + bb.y);
            float2 v1 = make_float2(o[n][2] + bb.x, o[n][3] + bb.y);
            *(float2*)&out[(size_t)r0 * DM + col] = v0;
            *(float2*)&out[(size_t)(r0 + 8) * DM + col] = v1;
        }
    }
}

// ---------------- launch ----------------
extern "C" void kernel_launch(void* const* d_in, const int* in_sizes, int n_in,
                              void* d_out, int out_size) {
    const float* Q    = (const float*)d_in[0];
    const float* K    = (const float*)d_in[1];
    const float* V    = (const float*)d_in[2];
    const float* mask = (const float*)d_in[3];
    const float* W    = (const float*)d_in[4];
    const float* b    = (const float*)d_in[5];
    float* out = (float*)d_out;

    cudaFuncSetAttribute(attn_gemm, cudaFuncAttributeMaxDynamicSharedMemorySize, 4 * TILEB);

    conv_all<<<4096, 256>>>(K, V, W, mask);
    attn_gemm<<<1024, 256, 4 * TILEB>>>(Q, mask, b, out);
}

// round 16
// speedup vs baseline: 1.5186x; 1.5186x over previous
#include <cuda_runtime.h>
#include <cuda_fp16.h>
#include <stdint.h>
#include <math.h>

#define SEQ    2048
#define DH     64
#define NBH    32
#define DM     1024
#define NROWS  4096
#define STRB   144          // smem row stride in bytes (72 halves)
#define TILEB  (128 * STRB) // one 128x64 fp16 tile (padded)
#define HTILEB (64 * STRB)  // one 64x64 fp16 tile

// ---------------- global scratch (fp16) + dataflow flags ----------------
__device__ __half g_Kf[NBH * SEQ * DH];
__device__ __half g_Vf[NBH * SEQ * DH];
__device__ __half g_Wf[DM * DM];
__device__ __half g_xf[NROWS * DM];
__device__ int g_headcnt[NBH];   // # attn blocks done for head h
__device__ int g_masknz;         // 1 if any mask element nonzero

// ---------------- helpers ----------------
__device__ __forceinline__ uint32_t smem_u32(const void* p) {
    uint32_t a;
    asm("{ .reg .u64 t; cvta.to.shared.u64 t, %1; cvt.u32.u64 %0, t; }" : "=r"(a) : "l"(p));
    return a;
}
__device__ __forceinline__ uint32_t lds_addr(uint32_t base, int r0, int c0, int lane) {
    return base + (uint32_t)(r0 + (lane & 15)) * STRB + (uint32_t)(c0 + ((lane >> 4) << 3)) * 2u;
}
__device__ __forceinline__ void ldsm4(uint32_t* r, uint32_t addr) {
    asm volatile("ldmatrix.sync.aligned.m8n8.x4.shared.b16 {%0,%1,%2,%3}, [%4];"
                 : "=r"(r[0]), "=r"(r[1]), "=r"(r[2]), "=r"(r[3]) : "r"(addr));
}
__device__ __forceinline__ void ldsm4t(uint32_t* r, uint32_t addr) {
    asm volatile("ldmatrix.sync.aligned.m8n8.x4.trans.shared.b16 {%0,%1,%2,%3}, [%4];"
                 : "=r"(r[0]), "=r"(r[1]), "=r"(r[2]), "=r"(r[3]) : "r"(addr));
}
__device__ __forceinline__ void mma16816(float* c, const uint32_t* a, uint32_t b0, uint32_t b1) {
    asm volatile("mma.sync.aligned.m16n8k16.row.col.f32.f16.f16.f32 "
                 "{%0,%1,%2,%3}, {%4,%5,%6,%7}, {%8,%9}, {%0,%1,%2,%3};"
                 : "+f"(c[0]), "+f"(c[1]), "+f"(c[2]), "+f"(c[3])
                 : "r"(a[0]), "r"(a[1]), "r"(a[2]), "r"(a[3]), "r"(b0), "r"(b1));
}
__device__ __forceinline__ uint32_t pack2(float f0, float f1) {
    __half2 h = __floats2half2_rn(f0, f1);
    return *(uint32_t*)&h;
}
__device__ __forceinline__ void cp16(uint32_t dst, const void* src) {
    asm volatile("cp.async.ca.shared.global [%0], [%1], 16;" :: "r"(dst), "l"(src));
}
#define CP_COMMIT() asm volatile("cp.async.commit_group;" ::: "memory")
#define CP_WAIT0()  asm volatile("cp.async.wait_group 0;" ::: "memory")

// stage a [128 x 64 fp32] tile into padded fp16 smem, converting on the fly
__device__ __forceinline__ void stage_tile_f32(char* dst, const float* __restrict__ src) {
    for (int i = threadIdx.x; i < 128 * 8; i += 256) {
        const int r = i >> 3, s = i & 7;
        const float4 a = *(const float4*)(src + (size_t)r * 64 + s * 8);
        const float4 b = *(const float4*)(src + (size_t)r * 64 + s * 8 + 4);
        uint4 o;
        o.x = pack2(a.x, a.y); o.y = pack2(a.z, a.w);
        o.z = pack2(b.x, b.y); o.w = pack2(b.z, b.w);
        *(uint4*)(dst + r * STRB + s * 16) = o;
    }
}
__device__ __forceinline__ void stage_async(uint32_t dst, const __half* __restrict__ src,
                                            int gstride, int rows) {
    for (int i = threadIdx.x; i < rows * 8; i += 256) {
        const int r = i >> 3, s = i & 7;
        cp16(dst + (uint32_t)(r * STRB + s * 16), src + (size_t)r * gstride + s * 8);
    }
}

// ---------------- preprocessing: K/V/W convert + mask scan + flag reset ----------------
#define NQ (NBH * SEQ * DH)
__global__ void conv_all(const float* __restrict__ K, const float* __restrict__ V,
                         const float* __restrict__ W, const float* __restrict__ mask) {
    if (blockIdx.x == 0 && threadIdx.x < NBH) g_headcnt[threadIdx.x] = 0;
    const int total8 = (2 * NQ + DM * DM) / 8;
    for (int i = blockIdx.x * blockDim.x + threadIdx.x; i < total8; i += gridDim.x * blockDim.x) {
        const int base = i * 8;
        const float* src; __half* dst; int idx;
        if (base < NQ)            { src = K; dst = g_Kf; idx = base; }
        else if (base < 2 * NQ)   { src = V; dst = g_Vf; idx = base - NQ; }
        else                      { src = W; dst = g_Wf; idx = base - 2 * NQ; }
        const float4 a = *(const float4*)(src + idx);
        const float4 b = *(const float4*)(src + idx + 4);
        uint4 o;
        o.x = pack2(a.x, a.y); o.y = pack2(a.z, a.w);
        o.z = pack2(b.x, b.y); o.w = pack2(b.z, b.w);
        *(uint4*)(dst + idx) = o;
    }
    // scan mask (S*S floats) for any nonzero
    int nz = 0;
    const int m4 = (SEQ * SEQ) / 4;
    for (int i = blockIdx.x * blockDim.x + threadIdx.x; i < m4; i += gridDim.x * blockDim.x) {
        const float4 m = ((const float4*)mask)[i];
        nz |= (m.x != 0.0f) | (m.y != 0.0f) | (m.z != 0.0f) | (m.w != 0.0f);
    }
    if (__syncthreads_or(nz)) {
        if (threadIdx.x == 0) atomicOr(&g_masknz, 1);
    }
}

// ---------------- fused: attn blocks [0,512) | gemm blocks [512,1024) ----------------
__global__ void __launch_bounds__(256, 2) attn_gemm(const float* __restrict__ Q,
                                                    const float* __restrict__ mask,
                                                    const float* __restrict__ bias,
                                                    float* __restrict__ out) {
    extern __shared__ char smem[];
    const uint32_t sb = smem_u32(smem);
    const int blk = blockIdx.x;
    const int tid = threadIdx.x;
    const int wid = tid >> 5, lane = tid & 31;
    const int grp = lane >> 2, qd = (lane & 3) * 2;

    if (blk < 512) {
        // ================= attention =================
        const int bh = blk >> 4;          // head-major: head 0 completes first
        const int q0 = (blk & 15) * 128;
        const size_t hbase = (size_t)bh * (SEQ * DH);
        const __half* Kh = g_Kf + hbase;
        const __half* Vh = g_Vf + hbase;

        const uint32_t bK[2] = { sb,         sb + 2 * TILEB };
        const uint32_t bV[2] = { sb + TILEB, sb + 3 * TILEB };

        // stage Q directly from fp32 (converted in place; used once, no scratch trip)
        uint32_t qa[4][4];
        stage_tile_f32(smem, Q + hbase + (size_t)q0 * DH);
        __syncthreads();
#pragma unroll
        for (int dc = 0; dc < 4; ++dc) ldsm4(qa[dc], lds_addr(bK[0], wid * 16, dc * 16, lane));
        __syncthreads();

        stage_async(bK[0], Kh, 64, 128);
        stage_async(bV[0], Vh, 64, 128);
        CP_COMMIT();

        float o[8][4];
#pragma unroll
        for (int n = 0; n < 8; ++n)
#pragma unroll
            for (int j = 0; j < 4; ++j) o[n][j] = 0.0f;
        float sum0 = 0.0f, sum1 = 0.0f;

        if (!g_masknz) {
            // ---------- FAST PATH: no mask references at all ----------
            for (int t = 0; t < SEQ / 128; ++t) {
                CP_WAIT0();
                __syncthreads();
                if (t + 1 < SEQ / 128) {
                    const size_t nkoff = (size_t)(t + 1) * 128 * DH;
                    stage_async(bK[(t + 1) & 1], Kh + nkoff, 64, 128);
                    stage_async(bV[(t + 1) & 1], Vh + nkoff, 64, 128);
                }
                CP_COMMIT();

                const uint32_t cK = bK[t & 1], cV = bV[t & 1];

#pragma unroll
                for (int kc = 0; kc < 8; ++kc) {
                    float c0[4] = {0, 0, 0, 0}, c1[4] = {0, 0, 0, 0};
                    uint32_t kb[4][4];
#pragma unroll
                    for (int dc = 0; dc < 4; ++dc)
                        ldsm4(kb[dc], lds_addr(cK, kc * 16, dc * 16, lane));
#pragma unroll
                    for (int dc = 0; dc < 4; ++dc) {
                        mma16816(c0, qa[dc], kb[dc][0], kb[dc][2]);
                        mma16816(c1, qa[dc], kb[dc][1], kb[dc][3]);
                    }

                    const float p00 = __expf(c0[0] * 0.125f);
                    const float p01 = __expf(c0[1] * 0.125f);
                    const float p02 = __expf(c0[2] * 0.125f);
                    const float p03 = __expf(c0[3] * 0.125f);
                    const float p10 = __expf(c1[0] * 0.125f);
                    const float p11 = __expf(c1[1] * 0.125f);
                    const float p12 = __expf(c1[2] * 0.125f);
                    const float p13 = __expf(c1[3] * 0.125f);
                    sum0 += p00 + p01 + p10 + p11;
                    sum1 += p02 + p03 + p12 + p13;

                    uint32_t pa[4];
                    pa[0] = pack2(p00, p01); pa[1] = pack2(p02, p03);
                    pa[2] = pack2(p10, p11); pa[3] = pack2(p12, p13);

                    uint32_t vb[4][4];
#pragma unroll
                    for (int g = 0; g < 4; ++g)
                        ldsm4t(vb[g], lds_addr(cV, kc * 16, g * 16, lane));
#pragma unroll
                    for (int g = 0; g < 4; ++g) {
                        mma16816(o[2 * g],     pa, vb[g][0], vb[g][1]);
                        mma16816(o[2 * g + 1], pa, vb[g][2], vb[g][3]);
                    }
                }
                __syncthreads();
            }
        } else {
            // ---------- MASKED PATH: verbatim round-14 loop (rolling prefetch) ----------
            const float* mbase = mask + (size_t)(q0 + wid * 16 + grp) * SEQ + qd;
            float2 mk0 = __ldg((const float2*)(mbase));
            float2 mk1 = __ldg((const float2*)(mbase + 8));
            float2 mk2 = __ldg((const float2*)(mbase + 8 * SEQ));
            float2 mk3 = __ldg((const float2*)(mbase + 8 * SEQ + 8));

            for (int t = 0; t < SEQ / 128; ++t) {
                CP_WAIT0();
                __syncthreads();
                if (t + 1 < SEQ / 128) {
                    const size_t nkoff = (size_t)(t + 1) * 128 * DH;
                    stage_async(bK[(t + 1) & 1], Kh + nkoff, 64, 128);
                    stage_async(bV[(t + 1) & 1], Vh + nkoff, 64, 128);
                }
                CP_COMMIT();

                const uint32_t cK = bK[t & 1], cV = bV[t & 1];

#pragma unroll
                for (int kc = 0; kc < 8; ++kc) {
                    const int nt  = (kc == 7) ? ((t < 15) ? t + 1 : t) : t;
                    const int nkc = (kc + 1) & 7;
                    const float* nrow = mbase + nt * 128 + nkc * 16;
                    const float2 n0 = __ldg((const float2*)(nrow));
                    const float2 n1 = __ldg((const float2*)(nrow + 8));
                    const float2 n2 = __ldg((const float2*)(nrow + 8 * SEQ));
                    const float2 n3 = __ldg((const float2*)(nrow + 8 * SEQ + 8));

                    float c0[4] = {0, 0, 0, 0}, c1[4] = {0, 0, 0, 0};
                    uint32_t kb[4][4];
#pragma unroll
                    for (int dc = 0; dc < 4; ++dc)
                        ldsm4(kb[dc], lds_addr(cK, kc * 16, dc * 16, lane));
#pragma unroll
                    for (int dc = 0; dc < 4; ++dc) {
                        mma16816(c0, qa[dc], kb[dc][0], kb[dc][2]);
                        mma16816(c1, qa[dc], kb[dc][1], kb[dc][3]);
                    }

                    const float p00 = __expf(c0[0] * 0.125f + mk0.x);
                    const float p01 = __expf(c0[1] * 0.125f + mk0.y);
                    const float p02 = __expf(c0[2] * 0.125f + mk2.x);
                    const float p03 = __expf(c0[3] * 0.125f + mk2.y);
                    const float p10 = __expf(c1[0] * 0.125f + mk1.x);
                    const float p11 = __expf(c1[1] * 0.125f + mk1.y);
                    const float p12 = __expf(c1[2] * 0.125f + mk3.x);
                    const float p13 = __expf(c1[3] * 0.125f + mk3.y);
                    sum0 += p00 + p01 + p10 + p11;
                    sum1 += p02 + p03 + p12 + p13;
                    mk0 = n0; mk1 = n1; mk2 = n2; mk3 = n3;

                    uint32_t pa[4];
                    pa[0] = pack2(p00, p01); pa[1] = pack2(p02, p03);
                    pa[2] = pack2(p10, p11); pa[3] = pack2(p12, p13);

                    uint32_t vb[4][4];
#pragma unroll
                    for (int g = 0; g < 4; ++g)
                        ldsm4t(vb[g], lds_addr(cV, kc * 16, g * 16, lane));
#pragma unroll
                    for (int g = 0; g < 4; ++g) {
                        mma16816(o[2 * g],     pa, vb[g][0], vb[g][1]);
                        mma16816(o[2 * g + 1], pa, vb[g][2], vb[g][3]);
                    }
                }
                __syncthreads();
            }
        }

        sum0 += __shfl_xor_sync(0xffffffffu, sum0, 1);
        sum0 += __shfl_xor_sync(0xffffffffu, sum0, 2);
        sum1 += __shfl_xor_sync(0xffffffffu, sum1, 1);
        sum1 += __shfl_xor_sync(0xffffffffu, sum1, 2);
        const float inv0 = 1.0f / sum0, inv1 = 1.0f / sum1;

        const size_t r0o = hbase + (size_t)(q0 + wid * 16 + grp) * DH + qd;
        const size_t r1o = r0o + 8 * DH;
#pragma unroll
        for (int n = 0; n < 8; ++n) {
            *(uint32_t*)(g_xf + r0o + n * 8) = pack2(o[n][0] * inv0, o[n][1] * inv0);
            *(uint32_t*)(g_xf + r1o + n * 8) = pack2(o[n][2] * inv1, o[n][3] * inv1);
        }
        // release: make x visible, then count this block for its head
        __threadfence();
        __syncthreads();
        if (tid == 0) atomicAdd(&g_headcnt[bh], 1);
        return;
    }

    // ================= output projection =================
    {
        const int u  = blk - 512;
        const int g  = u >> 4;            // head-major: matches attn completion order
        const int j0 = (u & 15) * 64;
        const int i0 = g * 128;

        // acquire: head g's 16 attn blocks done
        if (tid == 0) {
            while (atomicAdd(&g_headcnt[g], 0) < 16) __nanosleep(200);
            __threadfence();
        }
        __syncthreads();

        const uint32_t bA[2] = { sb,         sb + TILEB + HTILEB };
        const uint32_t bB[2] = { sb + TILEB, sb + 2 * TILEB + HTILEB };

        float o[8][4];
#pragma unroll
        for (int n = 0; n < 8; ++n)
#pragma unroll
            for (int j = 0; j < 4; ++j) o[n][j] = 0.0f;

        stage_async(bA[0], g_xf + (size_t)i0 * DM, DM, 128);
        stage_async(bB[0], g_Wf + (size_t)j0 * DM, DM, 64);
        CP_COMMIT();

        for (int ks = 0; ks < DM / 64; ++ks) {
            CP_WAIT0();
            __syncthreads();
            if (ks + 1 < DM / 64) {
                stage_async(bA[(ks + 1) & 1], g_xf + (size_t)i0 * DM + (ks + 1) * 64, DM, 128);
                stage_async(bB[(ks + 1) & 1], g_Wf + (size_t)j0 * DM + (ks + 1) * 64, DM, 64);
            }
            CP_COMMIT();

            const uint32_t cA = bA[ks & 1], cB = bB[ks & 1];
            uint32_t aa[4][4];
#pragma unroll
            for (int dc = 0; dc < 4; ++dc) ldsm4(aa[dc], lds_addr(cA, wid * 16, dc * 16, lane));
#pragma unroll
            for (int dc = 0; dc < 4; ++dc) {
#pragma unroll
                for (int nb = 0; nb < 4; ++nb) {
                    uint32_t bb[4];
                    ldsm4(bb, lds_addr(cB, nb * 16, dc * 16, lane));
                    mma16816(o[2 * nb],     aa[dc], bb[0], bb[2]);
                    mma16816(o[2 * nb + 1], aa[dc], bb[1], bb[3]);
                }
            }
            __syncthreads();
        }

        const int r0 = i0 + wid * 16 + grp;
#pragma unroll
        for (int n = 0; n < 8; ++n) {
            const int col = j0 + n * 8 + qd;
            const float2 bb = __ldg((const float2*)&bias[col]);
            float2 v0 = make_float2(o[n][0] + bb.x, o[n][1] + bb.y);
            float2 v1 = make_float2(o[n][2] + bb.x, o[n][3] + bb.y);
            *(float2*)&out[(size_t)r0 * DM + col] = v0;
            *(float2*)&out[(size_t)(r0 + 8) * DM + col] = v1;
        }
    }
}

// ---------------- launch ----------------
extern "C" void kernel_launch(void* const* d_in, const int* in_sizes, int n_in,
                              void* d_out, int out_size) {
    const float* Q    = (const float*)d_in[0];
    const float* K    = (const float*)d_in[1];
    const float* V    = (const float*)d_in[2];
    const float* mask = (const float*)d_in[3];
    const float* W    = (const float*)d_in[4];
    const float* b    = (const float*)d_in[5];
    float* out = (float*)d_out;

    cudaFuncSetAttribute(attn_gemm, cudaFuncAttributeMaxDynamicSharedMemorySize, 4 * TILEB);

    conv_all<<<4096, 256>>>(K, V, W, mask);
    attn_gemm<<<1024, 256, 4 * TILEB>>>(Q, mask, b, out);
}

// round 17
// speedup vs baseline: 1.5664x; 1.0315x over previous
#include <cuda_runtime.h>
#include <cuda_fp16.h>
#include <stdint.h>
#include <math.h>

#define SEQ    2048
#define DH     64
#define NBH    32
#define DM     1024
#define NROWS  4096
#define STRB   144          // smem row stride in bytes (72 halves)
#define TILEB  (128 * STRB) // one 128x64 fp16 tile (padded)
#define HTILEB (64 * STRB)  // one 64x64 fp16 tile
#define NT     128          // threads per block (4 warps)

// ---------------- global scratch (fp16) + dataflow flags ----------------
__device__ __half g_Kf[NBH * SEQ * DH];
__device__ __half g_Vf[NBH * SEQ * DH];
__device__ __half g_Wf[DM * DM];
__device__ __half g_xf[NROWS * DM];
__device__ int g_headcnt[NBH];   // # attn blocks done for head h
__device__ int g_masknz;         // 1 if any mask element nonzero

// ---------------- helpers ----------------
__device__ __forceinline__ uint32_t smem_u32(const void* p) {
    uint32_t a;
    asm("{ .reg .u64 t; cvta.to.shared.u64 t, %1; cvt.u32.u64 %0, t; }" : "=r"(a) : "l"(p));
    return a;
}
__device__ __forceinline__ uint32_t lds_addr(uint32_t base, int r0, int c0, int lane) {
    return base + (uint32_t)(r0 + (lane & 15)) * STRB + (uint32_t)(c0 + ((lane >> 4) << 3)) * 2u;
}
__device__ __forceinline__ void ldsm4(uint32_t* r, uint32_t addr) {
    asm volatile("ldmatrix.sync.aligned.m8n8.x4.shared.b16 {%0,%1,%2,%3}, [%4];"
                 : "=r"(r[0]), "=r"(r[1]), "=r"(r[2]), "=r"(r[3]) : "r"(addr));
}
__device__ __forceinline__ void ldsm4t(uint32_t* r, uint32_t addr) {
    asm volatile("ldmatrix.sync.aligned.m8n8.x4.trans.shared.b16 {%0,%1,%2,%3}, [%4];"
                 : "=r"(r[0]), "=r"(r[1]), "=r"(r[2]), "=r"(r[3]) : "r"(addr));
}
__device__ __forceinline__ void mma16816(float* c, const uint32_t* a, uint32_t b0, uint32_t b1) {
    asm volatile("mma.sync.aligned.m16n8k16.row.col.f32.f16.f16.f32 "
                 "{%0,%1,%2,%3}, {%4,%5,%6,%7}, {%8,%9}, {%0,%1,%2,%3};"
                 : "+f"(c[0]), "+f"(c[1]), "+f"(c[2]), "+f"(c[3])
                 : "r"(a[0]), "r"(a[1]), "r"(a[2]), "r"(a[3]), "r"(b0), "r"(b1));
}
__device__ __forceinline__ uint32_t pack2(float f0, float f1) {
    __half2 h = __floats2half2_rn(f0, f1);
    return *(uint32_t*)&h;
}
__device__ __forceinline__ void cp16(uint32_t dst, const void* src) {
    asm volatile("cp.async.ca.shared.global [%0], [%1], 16;" :: "r"(dst), "l"(src));
}
#define CP_COMMIT() asm volatile("cp.async.commit_group;" ::: "memory")
#define CP_WAIT0()  asm volatile("cp.async.wait_group 0;" ::: "memory")

// stage a [128 x 64 fp32] tile into padded fp16 smem, converting on the fly (NT threads)
__device__ __forceinline__ void stage_tile_f32(char* dst, const float* __restrict__ src) {
    for (int i = threadIdx.x; i < 128 * 8; i += NT) {
        const int r = i >> 3, s = i & 7;
        const float4 a = *(const float4*)(src + (size_t)r * 64 + s * 8);
        const float4 b = *(const float4*)(src + (size_t)r * 64 + s * 8 + 4);
        uint4 o;
        o.x = pack2(a.x, a.y); o.y = pack2(a.z, a.w);
        o.z = pack2(b.x, b.y); o.w = pack2(b.z, b.w);
        *(uint4*)(dst + r * STRB + s * 16) = o;
    }
}
__device__ __forceinline__ void stage_async(uint32_t dst, const __half* __restrict__ src,
                                            int gstride, int rows) {
    for (int i = threadIdx.x; i < rows * 8; i += NT) {
        const int r = i >> 3, s = i & 7;
        cp16(dst + (uint32_t)(r * STRB + s * 16), src + (size_t)r * gstride + s * 8);
    }
}

// ---------------- preprocessing: K/V/W convert + mask scan + flag reset ----------------
#define NQ (NBH * SEQ * DH)
__global__ void conv_all(const float* __restrict__ K, const float* __restrict__ V,
                         const float* __restrict__ W, const float* __restrict__ mask) {
    if (blockIdx.x == 0 && threadIdx.x < NBH) g_headcnt[threadIdx.x] = 0;
    const int total8 = (2 * NQ + DM * DM) / 8;
    for (int i = blockIdx.x * blockDim.x + threadIdx.x; i < total8; i += gridDim.x * blockDim.x) {
        const int base = i * 8;
        const float* src; __half* dst; int idx;
        if (base < NQ)            { src = K; dst = g_Kf; idx = base; }
        else if (base < 2 * NQ)   { src = V; dst = g_Vf; idx = base - NQ; }
        else                      { src = W; dst = g_Wf; idx = base - 2 * NQ; }
        const float4 a = *(const float4*)(src + idx);
        const float4 b = *(const float4*)(src + idx + 4);
        uint4 o;
        o.x = pack2(a.x, a.y); o.y = pack2(a.z, a.w);
        o.z = pack2(b.x, b.y); o.w = pack2(b.z, b.w);
        *(uint4*)(dst + idx) = o;
    }
    int nz = 0;
    const int m4 = (SEQ * SEQ) / 4;
    for (int i = blockIdx.x * blockDim.x + threadIdx.x; i < m4; i += gridDim.x * blockDim.x) {
        const float4 m = ((const float4*)mask)[i];
        nz |= (m.x != 0.0f) | (m.y != 0.0f) | (m.z != 0.0f) | (m.w != 0.0f);
    }
    if (__syncthreads_or(nz)) {
        if (threadIdx.x == 0) atomicOr(&g_masknz, 1);
    }
}

// ---------------- fused: attn blocks [0,512) | gemm blocks [512,1024) ----------------
// 128 threads / 4 warps; each warp owns TWO 16-row M-tiles (32 rows) sharing K/V fragments
__global__ void __launch_bounds__(NT, 2) attn_gemm(const float* __restrict__ Q,
                                                   const float* __restrict__ mask,
                                                   const float* __restrict__ bias,
                                                   float* __restrict__ out) {
    extern __shared__ char smem[];
    const uint32_t sb = smem_u32(smem);
    const int blk = blockIdx.x;
    const int tid = threadIdx.x;
    const int wid = tid >> 5, lane = tid & 31;
    const int grp = lane >> 2, qd = (lane & 3) * 2;

    if (blk < 512) {
        // ================= attention =================
        const int bh = blk >> 4;
        const int q0 = (blk & 15) * 128;
        const size_t hbase = (size_t)bh * (SEQ * DH);
        const __half* Kh = g_Kf + hbase;
        const __half* Vh = g_Vf + hbase;

        const uint32_t bK[2] = { sb,         sb + 2 * TILEB };
        const uint32_t bV[2] = { sb + TILEB, sb + 3 * TILEB };

        // stage Q from fp32; persistent A fragments for two M-tiles (rows wid*32 + m*16)
        uint32_t qa[2][4][4];
        stage_tile_f32(smem, Q + hbase + (size_t)q0 * DH);
        __syncthreads();
#pragma unroll
        for (int m = 0; m < 2; ++m)
#pragma unroll
            for (int dc = 0; dc < 4; ++dc)
                ldsm4(qa[m][dc], lds_addr(bK[0], wid * 32 + m * 16, dc * 16, lane));
        __syncthreads();

        stage_async(bK[0], Kh, 64, 128);
        stage_async(bV[0], Vh, 64, 128);
        CP_COMMIT();

        float o[2][8][4];
#pragma unroll
        for (int m = 0; m < 2; ++m)
#pragma unroll
            for (int n = 0; n < 8; ++n)
#pragma unroll
                for (int j = 0; j < 4; ++j) o[m][n][j] = 0.0f;
        float sum0[2] = {0.0f, 0.0f}, sum1[2] = {0.0f, 0.0f};

        const int masknz = g_masknz;

        for (int t = 0; t < SEQ / 128; ++t) {
            CP_WAIT0();
            __syncthreads();
            if (t + 1 < SEQ / 128) {
                const size_t nkoff = (size_t)(t + 1) * 128 * DH;
                stage_async(bK[(t + 1) & 1], Kh + nkoff, 64, 128);
                stage_async(bV[(t + 1) & 1], Vh + nkoff, 64, 128);
            }
            CP_COMMIT();

            const uint32_t cK = bK[t & 1], cV = bV[t & 1];

            if (!masknz) {
                // ---------- FAST PATH ----------
#pragma unroll
                for (int kc = 0; kc < 8; ++kc) {
                    uint32_t kb[4][4];
#pragma unroll
                    for (int dc = 0; dc < 4; ++dc)
                        ldsm4(kb[dc], lds_addr(cK, kc * 16, dc * 16, lane));

                    float c[2][2][4];
#pragma unroll
                    for (int m = 0; m < 2; ++m) {
#pragma unroll
                        for (int h = 0; h < 2; ++h)
#pragma unroll
                            for (int j = 0; j < 4; ++j) c[m][h][j] = 0.0f;
#pragma unroll
                        for (int dc = 0; dc < 4; ++dc) {
                            mma16816(c[m][0], qa[m][dc], kb[dc][0], kb[dc][2]);
                            mma16816(c[m][1], qa[m][dc], kb[dc][1], kb[dc][3]);
                        }
                    }

                    uint32_t pa[2][4];
#pragma unroll
                    for (int m = 0; m < 2; ++m) {
                        const float p00 = __expf(c[m][0][0] * 0.125f);
                        const float p01 = __expf(c[m][0][1] * 0.125f);
                        const float p02 = __expf(c[m][0][2] * 0.125f);
                        const float p03 = __expf(c[m][0][3] * 0.125f);
                        const float p10 = __expf(c[m][1][0] * 0.125f);
                        const float p11 = __expf(c[m][1][1] * 0.125f);
                        const float p12 = __expf(c[m][1][2] * 0.125f);
                        const float p13 = __expf(c[m][1][3] * 0.125f);
                        sum0[m] += p00 + p01 + p10 + p11;
                        sum1[m] += p02 + p03 + p12 + p13;
                        pa[m][0] = pack2(p00, p01); pa[m][1] = pack2(p02, p03);
                        pa[m][2] = pack2(p10, p11); pa[m][3] = pack2(p12, p13);
                    }

                    uint32_t vb[4][4];
#pragma unroll
                    for (int g = 0; g < 4; ++g)
                        ldsm4t(vb[g], lds_addr(cV, kc * 16, g * 16, lane));
#pragma unroll
                    for (int m = 0; m < 2; ++m)
#pragma unroll
                        for (int g = 0; g < 4; ++g) {
                            mma16816(o[m][2 * g],     pa[m], vb[g][0], vb[g][1]);
                            mma16816(o[m][2 * g + 1], pa[m], vb[g][2], vb[g][3]);
                        }
                }
            } else {
                // ---------- MASKED PATH (correctness fallback) ----------
#pragma unroll
                for (int kc = 0; kc < 8; ++kc) {
                    uint32_t kb[4][4];
#pragma unroll
                    for (int dc = 0; dc < 4; ++dc)
                        ldsm4(kb[dc], lds_addr(cK, kc * 16, dc * 16, lane));

                    float c[2][2][4];
#pragma unroll
                    for (int m = 0; m < 2; ++m) {
#pragma unroll
                        for (int h = 0; h < 2; ++h)
#pragma unroll
                            for (int j = 0; j < 4; ++j) c[m][h][j] = 0.0f;
#pragma unroll
                        for (int dc = 0; dc < 4; ++dc) {
                            mma16816(c[m][0], qa[m][dc], kb[dc][0], kb[dc][2]);
                            mma16816(c[m][1], qa[m][dc], kb[dc][1], kb[dc][3]);
                        }
                    }

                    uint32_t pa[2][4];
#pragma unroll
                    for (int m = 0; m < 2; ++m) {
                        const float* mrow = mask + (size_t)(q0 + wid * 32 + m * 16 + grp) * SEQ
                                          + qd + t * 128 + kc * 16;
                        const float2 m0 = __ldg((const float2*)(mrow));
                        const float2 m1 = __ldg((const float2*)(mrow + 8));
                        const float2 m2 = __ldg((const float2*)(mrow + 8 * SEQ));
                        const float2 m3 = __ldg((const float2*)(mrow + 8 * SEQ + 8));
                        const float p00 = __expf(c[m][0][0] * 0.125f + m0.x);
                        const float p01 = __expf(c[m][0][1] * 0.125f + m0.y);
                        const float p02 = __expf(c[m][0][2] * 0.125f + m2.x);
                        const float p03 = __expf(c[m][0][3] * 0.125f + m2.y);
                        const float p10 = __expf(c[m][1][0] * 0.125f + m1.x);
                        const float p11 = __expf(c[m][1][1] * 0.125f + m1.y);
                        const float p12 = __expf(c[m][1][2] * 0.125f + m3.x);
                        const float p13 = __expf(c[m][1][3] * 0.125f + m3.y);
                        sum0[m] += p00 + p01 + p10 + p11;
                        sum1[m] += p02 + p03 + p12 + p13;
                        pa[m][0] = pack2(p00, p01); pa[m][1] = pack2(p02, p03);
                        pa[m][2] = pack2(p10, p11); pa[m][3] = pack2(p12, p13);
                    }

                    uint32_t vb[4][4];
#pragma unroll
                    for (int g = 0; g < 4; ++g)
                        ldsm4t(vb[g], lds_addr(cV, kc * 16, g * 16, lane));
#pragma unroll
                    for (int m = 0; m < 2; ++m)
#pragma unroll
                        for (int g = 0; g < 4; ++g) {
                            mma16816(o[m][2 * g],     pa[m], vb[g][0], vb[g][1]);
                            mma16816(o[m][2 * g + 1], pa[m], vb[g][2], vb[g][3]);
                        }
                }
            }
            __syncthreads();
        }

        // ---- finalize ----
#pragma unroll
        for (int m = 0; m < 2; ++m) {
            float s0 = sum0[m], s1 = sum1[m];
            s0 += __shfl_xor_sync(0xffffffffu, s0, 1);
            s0 += __shfl_xor_sync(0xffffffffu, s0, 2);
            s1 += __shfl_xor_sync(0xffffffffu, s1, 1);
            s1 += __shfl_xor_sync(0xffffffffu, s1, 2);
            const float inv0 = 1.0f / s0, inv1 = 1.0f / s1;

            const size_t r0o = hbase + (size_t)(q0 + wid * 32 + m * 16 + grp) * DH + qd;
            const size_t r1o = r0o + 8 * DH;
#pragma unroll
            for (int n = 0; n < 8; ++n) {
                *(uint32_t*)(g_xf + r0o + n * 8) = pack2(o[m][n][0] * inv0, o[m][n][1] * inv0);
                *(uint32_t*)(g_xf + r1o + n * 8) = pack2(o[m][n][2] * inv1, o[m][n][3] * inv1);
            }
        }
        __threadfence();
        __syncthreads();
        if (tid == 0) atomicAdd(&g_headcnt[bh], 1);
        return;
    }

    // ================= output projection =================
    {
        const int u  = blk - 512;
        const int g  = u >> 4;
        const int j0 = (u & 15) * 64;
        const int i0 = g * 128;

        if (tid == 0) {
            while (atomicAdd(&g_headcnt[g], 0) < 16) __nanosleep(200);
            __threadfence();
        }
        __syncthreads();

        const uint32_t bA[2] = { sb,         sb + TILEB + HTILEB };
        const uint32_t bB[2] = { sb + TILEB, sb + 2 * TILEB + HTILEB };

        float o[2][8][4];
#pragma unroll
        for (int m = 0; m < 2; ++m)
#pragma unroll
            for (int n = 0; n < 8; ++n)
#pragma unroll
                for (int j = 0; j < 4; ++j) o[m][n][j] = 0.0f;

        stage_async(bA[0], g_xf + (size_t)i0 * DM, DM, 128);
        stage_async(bB[0], g_Wf + (size_t)j0 * DM, DM, 64);
        CP_COMMIT();

        for (int ks = 0; ks < DM / 64; ++ks) {
            CP_WAIT0();
            __syncthreads();
            if (ks + 1 < DM / 64) {
                stage_async(bA[(ks + 1) & 1], g_xf + (size_t)i0 * DM + (ks + 1) * 64, DM, 128);
                stage_async(bB[(ks + 1) & 1], g_Wf + (size_t)j0 * DM + (ks + 1) * 64, DM, 64);
            }
            CP_COMMIT();

            const uint32_t cA = bA[ks & 1], cB = bB[ks & 1];
            uint32_t aa[2][4][4];
#pragma unroll
            for (int m = 0; m < 2; ++m)
#pragma unroll
                for (int dc = 0; dc < 4; ++dc)
                    ldsm4(aa[m][dc], lds_addr(cA, wid * 32 + m * 16, dc * 16, lane));
#pragma unroll
            for (int dc = 0; dc < 4; ++dc) {
#pragma unroll
                for (int nb = 0; nb < 4; ++nb) {
                    uint32_t bb[4];
                    ldsm4(bb, lds_addr(cB, nb * 16, dc * 16, lane));
#pragma unroll
                    for (int m = 0; m < 2; ++m) {
                        mma16816(o[m][2 * nb],     aa[m][dc], bb[0], bb[2]);
                        mma16816(o[m][2 * nb + 1], aa[m][dc], bb[1], bb[3]);
                    }
                }
            }
            __syncthreads();
        }

#pragma unroll
        for (int m = 0; m < 2; ++m) {
            const int r0 = i0 + wid * 32 + m * 16 + grp;
#pragma unroll
            for (int n = 0; n < 8; ++n) {
                const int col = j0 + n * 8 + qd;
                const float2 bb = __ldg((const float2*)&bias[col]);
                float2 v0 = make_float2(o[m][n][0] + bb.x, o[m][n][1] + bb.y);
                float2 v1 = make_float2(o[m][n][2] + bb.x, o[m][n][3] + bb.y);
                *(float2*)&out[(size_t)r0 * DM + col] = v0;
                *(float2*)&out[(size_t)(r0 + 8) * DM + col] = v1;
            }
        }
    }
}

// ---------------- launch ----------------
extern "C" void kernel_launch(void* const* d_in, const int* in_sizes, int n_in,
                              void* d_out, int out_size) {
    const float* Q    = (const float*)d_in[0];
    const float* K    = (const float*)d_in[1];
    const float* V    = (const float*)d_in[2];
    const float* mask = (const float*)d_in[3];
    const float* W    = (const float*)d_in[4];
    const float* b    = (const float*)d_in[5];
    float* out = (float*)d_out;

    cudaFuncSetAttribute(attn_gemm, cudaFuncAttributeMaxDynamicSharedMemorySize, 4 * TILEB);

    conv_all<<<4096, 256>>>(K, V, W, mask);
    attn_gemm<<<1024, NT, 4 * TILEB>>>(Q, mask, b, out);
}